// round 7
// baseline (speedup 1.0000x reference)
#include <cuda_runtime.h>
#include <cuda_fp16.h>
#include <cstdint>

// ---------------------------------------------------------------------------
// Problem constants
// ---------------------------------------------------------------------------
#define Bn     32
#define Nn     2048
#define PDn    2
#define LATn   128
#define Hn     256
#define STEPSn 5
#define DINn   131
#define NPTS   (Bn * Nn)         // 65536
#define PPC    64                // points per CTA (= GEMM M)
#define NCTA   (NPTS / PPC)      // 1024
#define KCH    32                // K-chunk
#define NCHUNK (Hn / KCH)        // 8
#define NTHREADS 512

// ---------------------------------------------------------------------------
// Device globals
// ---------------------------------------------------------------------------
// Padded B image: per chunk 40960 B = [W2: 256 rows x 80B] [M: 256 rows x 80B]
// (64B of fp16 k-data + 16B pad per row; pad zeroed, never read by MMA)
__device__ __align__(16) uint8_t g_Wimg[NCHUNK * 40960];
__device__ __align__(16) float g_base[Bn * Hn];
__device__ __align__(16) float g_c0[Hn], g_c1[Hn], g_ct[Hn], g_csum[Hn];

__device__ __forceinline__ float ftanh(float x) {
    float e = __expf(2.0f * x);
    return 1.0f - __fdividef(2.0f, e + 1.0f);
}
__device__ __forceinline__ uint32_t smem_u32(const void* p) {
    uint32_t a;
    asm("{ .reg .u64 t; cvta.to.shared.u64 t, %1; cvt.u32.u64 %0, t; }"
        : "=r"(a) : "l"(p));
    return a;
}
__device__ __forceinline__ void ldsm4(uint32_t& r0, uint32_t& r1,
                                      uint32_t& r2, uint32_t& r3, uint32_t addr) {
    asm volatile("ldmatrix.sync.aligned.m8n8.x4.shared.b16 {%0,%1,%2,%3}, [%4];"
                 : "=r"(r0), "=r"(r1), "=r"(r2), "=r"(r3) : "r"(addr));
}
__device__ __forceinline__ void mma16816(float* d, const uint32_t* a,
                                         uint32_t b0, uint32_t b1) {
    asm volatile(
        "mma.sync.aligned.m16n8k16.row.col.f32.f16.f16.f32 "
        "{%0,%1,%2,%3},{%4,%5,%6,%7},{%8,%9},{%0,%1,%2,%3};"
        : "+f"(d[0]), "+f"(d[1]), "+f"(d[2]), "+f"(d[3])
        : "r"(a[0]), "r"(a[1]), "r"(a[2]), "r"(a[3]), "r"(b0), "r"(b1));
}
__device__ __forceinline__ void cp16(uint32_t dst, const void* src) {
    asm volatile("cp.async.cg.shared.global [%0], [%1], 16;"
                 :: "r"(dst), "l"(src));
}
#define CP_COMMIT() asm volatile("cp.async.commit_group;" ::: "memory")
#define CP_WAIT0()  asm volatile("cp.async.wait_group 0;" ::: "memory")

// ---------------------------------------------------------------------------
// Precompute 1: per-row W1 decomposition + per-batch base vectors
// ---------------------------------------------------------------------------
__global__ void precomp_aux(const float* __restrict__ W1,
                            const float* __restrict__ b1,
                            const float* __restrict__ z) {
    int k = threadIdx.x;
    int b = blockIdx.x;
    const float* row = W1 + k * DINn;
    float d = b1[k];
    const float* zb = z + b * LATn;
#pragma unroll 16
    for (int l = 0; l < LATn; ++l) d += row[3 + l] * zb[l];
    g_base[b * Hn + k] = d;
    if (b == 0) {
        float s = 0.f;
#pragma unroll 16
        for (int l = 0; l < LATn; ++l) s += row[3 + l];
        g_c0[k] = row[0]; g_c1[k] = row[1]; g_ct[k] = row[2]; g_csum[k] = s;
    }
}

// ---------------------------------------------------------------------------
// Precompute 2: W2 + fused divergence matrix M -> fp16 padded chunk image
// ---------------------------------------------------------------------------
__global__ void precomp_w(const float* __restrict__ W1,
                          const float* __restrict__ W2,
                          const float* __restrict__ W3) {
    int j = blockIdx.x;   // 256
    int k = threadIdx.x;  // 256
    float w2 = W2[j * Hn + k];
    float mm = w2 * (W1[k * DINn] * W3[j] + W1[k * DINn + 1] * W3[Hn + j]);
    int chunk = k >> 5, kk = k & 31;
    uint8_t* base = g_Wimg + chunk * 40960 + j * 80;
    *reinterpret_cast<__half*>(base + kk * 2) = __float2half_rn(w2);
    *reinterpret_cast<__half*>(base + 20480 + kk * 2) = __float2half_rn(mm);
    if (kk < 8) {  // zero pads
        *reinterpret_cast<__half*>(base + 64 + kk * 2) = __float2half_rn(0.f);
        *reinterpret_cast<__half*>(base + 20480 + 64 + kk * 2) = __float2half_rn(0.f);
    }
}

// ---------------------------------------------------------------------------
// SMEM layout (byte offsets)
// ---------------------------------------------------------------------------
#define SM_C0    0
#define SM_C1    1024
#define SM_CT    2048
#define SM_CS    3072
#define SM_BASE  4096
#define SM_B2    5120
#define SM_W30   6144
#define SM_W31   7168
#define SM_X0    8192          // 64 f32
#define SM_X1    8448
#define SM_SS    8704
#define SM_PART  8960          // [3][8][64] f32 = 6144 -> end 15104
#define SM_AH    15360         // 64 x 528 B = 33792 (h hi)
#define SM_AL    49152         // 33792 (h lo)
#define SM_AG    82944         // 33792 (g, single fp16)
#define SM_B     116736        // 2 bufs x 40960
#define SM_TOTAL 198656

#define A_STRIDE 528
#define B_STRIDE 80

// ---------------------------------------------------------------------------
// Main fused CNF kernel: single pass/step, merged dual-GEMM, cp.async B stream
// ---------------------------------------------------------------------------
__global__ void __launch_bounds__(NTHREADS, 1)
cnf_kernel(const float* __restrict__ x,
           const float* __restrict__ b2,
           const float* __restrict__ W3,
           const float* __restrict__ b3,
           const float* __restrict__ osc,
           float* __restrict__ out,
           int out_size) {
    extern __shared__ char smem[];
    float* sf = reinterpret_cast<float*>(smem);
    const uint32_t sb = smem_u32(smem);

    const int tid  = threadIdx.x;
    const int wid  = tid >> 5;
    const int lane = tid & 31;
    const int gp0  = blockIdx.x * PPC;
    const int bidx = gp0 >> 11;

    // constants -> smem
    if (tid < Hn) {
        sf[(SM_C0 >> 2) + tid]   = g_c0[tid];
        sf[(SM_C1 >> 2) + tid]   = g_c1[tid];
        sf[(SM_CT >> 2) + tid]   = g_ct[tid];
        sf[(SM_CS >> 2) + tid]   = g_csum[tid];
        sf[(SM_BASE >> 2) + tid] = g_base[bidx * Hn + tid];
        sf[(SM_B2 >> 2) + tid]   = b2[tid];
        sf[(SM_W30 >> 2) + tid]  = W3[tid];
        sf[(SM_W31 >> 2) + tid]  = W3[Hn + tid];
    }
    if (tid < PPC) {
        int gp = gp0 + tid;
        sf[(SM_X0 >> 2) + tid] = x[gp * 2 + 0];
        sf[(SM_X1 >> 2) + tid] = x[gp * 2 + 1];
        sf[(SM_SS >> 2) + tid] = 0.f;
    }

#define ISSUE_B(chunk, buf) do {                                          \
        const uint8_t* _src = g_Wimg + (chunk) * 40960;                    \
        uint32_t _dst = sb + SM_B + (uint32_t)(buf) * 40960u;              \
        _Pragma("unroll")                                                  \
        for (int _i = 0; _i < 5; ++_i) {                                   \
            int _idx = _i * NTHREADS + tid;                                \
            cp16(_dst + (uint32_t)_idx * 16u, _src + _idx * 16);           \
        }                                                                  \
        CP_COMMIT();                                                       \
    } while (0)

    // prologue: B(0) for step 0 (overlaps const setup + layer-1)
    ISSUE_B(0, 0);
    __syncthreads();

    const float scale = __ldg(osc);
    const float dt  = 1.0f / (float)STEPSn;
    const float b30 = __ldg(b3), b31 = __ldg(b3 + 1);

    // layer-1 mapping: 64 points x 8 k-groups of 32
    const int p_mine = tid >> 3;
    const int kq     = tid & 7;
    // mma warp tiling: 2 (M) x 8 (N); warp tile 32 x 32
    const int warp_m = wid >> 3;
    const int warp_n = wid & 7;
    const int m0w = warp_m * 32;
    const int n0w = warp_n * 32;
    const int grp = lane >> 2, tig = lane & 3;
    const uint32_t aoff = (uint32_t)(lane & 15) * A_STRIDE + ((uint32_t)(lane >> 4) << 4);
    const uint32_t boff = ((uint32_t)((lane & 7) + ((lane >> 4) << 3))) * B_STRIDE
                        + (((uint32_t)(lane >> 3) & 1u) << 4);

    const float* c0s = sf + (SM_C0 >> 2);
    const float* c1s = sf + (SM_C1 >> 2);
    const float* cts = sf + (SM_CT >> 2);
    const float* css = sf + (SM_CS >> 2);
    const float* bas = sf + (SM_BASE >> 2);
    const float* b2s = sf + (SM_B2 >> 2);
    const float* w30s = sf + (SM_W30 >> 2);
    const float* w31s = sf + (SM_W31 >> 2);
    float* part = sf + (SM_PART >> 2);

#pragma unroll 1
    for (int step = 0; step < STEPSn; ++step) {
        const float tcur = dt * (float)step;
        const float px0 = sf[(SM_X0 >> 2) + p_mine];
        const float px1 = sf[(SM_X1 >> 2) + p_mine];
        const float psv = sf[(SM_SS >> 2) + p_mine];

        // ---- layer 1: all 256 k at once (h hi/lo + g fp16), tanh ONCE ----
        {
            const int kb = kq * 32;
#pragma unroll
            for (int i = 0; i < 32; i += 2) {
                int k = kb + i;
                float u0 = bas[k] + tcur * cts[k] + psv * css[k]
                         + px0 * c0s[k] + px1 * c1s[k];
                float u1 = bas[k+1] + tcur * cts[k+1] + psv * css[k+1]
                         + px0 * c0s[k+1] + px1 * c1s[k+1];
                float h0 = ftanh(u0), h1 = ftanh(u1);
                float g0 = 1.f - h0 * h0, g1 = 1.f - h1 * h1;
                __half H0 = __float2half_rn(h0);
                __half H1 = __float2half_rn(h1);
                __half L0 = __float2half_rn(h0 - __half2float(H0));
                __half L1 = __float2half_rn(h1 - __half2float(H1));
                uint32_t o = (uint32_t)p_mine * A_STRIDE + (uint32_t)k * 2u;
                *reinterpret_cast<__half2*>(smem + SM_AH + o) = __halves2half2(H0, H1);
                *reinterpret_cast<__half2*>(smem + SM_AL + o) = __halves2half2(L0, L1);
                *reinterpret_cast<__half2*>(smem + SM_AG + o) = __floats2half2_rn(g0, g1);
            }
        }
        __syncthreads();   // A tiles visible to all warps

        float accA[2][4][4], accD[2][4][4];
#pragma unroll
        for (int mi = 0; mi < 2; ++mi)
#pragma unroll
            for (int ni = 0; ni < 4; ++ni)
#pragma unroll
                for (int q = 0; q < 4; ++q) { accA[mi][ni][q] = 0.f; accD[mi][ni][q] = 0.f; }

        // ---- chunk loop: stream B, 3 GEMM terms per chunk ----
#pragma unroll 1
        for (int c = 0; c < NCHUNK; ++c) {
            CP_WAIT0();
            __syncthreads();   // all warps done with previous chunk's buffer
            if (c + 1 < NCHUNK) ISSUE_B(c + 1, (c + 1) & 1);

            const uint32_t bb = sb + SM_B + (uint32_t)(c & 1) * 40960u;
            const uint32_t coff = (uint32_t)c * 64u;   // 32 k * 2B

#pragma unroll
            for (int term = 0; term < 3; ++term) {
                const uint32_t ab = sb + (term == 0 ? SM_AH : (term == 1 ? SM_AL : SM_AG)) + coff;
                const uint32_t bt = (term == 2) ? (bb + 20480u) : bb;
                float (*acc)[4][4] = (term == 2) ? accD : accA;
#pragma unroll
                for (int ks = 0; ks < 2; ++ks) {
                    uint32_t a[2][4];
#pragma unroll
                    for (int mi = 0; mi < 2; ++mi) {
                        uint32_t ad = ab + (uint32_t)(m0w + mi * 16) * A_STRIDE
                                    + (uint32_t)ks * 32u + aoff;
                        ldsm4(a[mi][0], a[mi][1], a[mi][2], a[mi][3], ad);
                    }
#pragma unroll
                    for (int ng = 0; ng < 2; ++ng) {
                        uint32_t r0, r1, r2, r3;
                        uint32_t bd = bt + (uint32_t)(n0w + ng * 16) * B_STRIDE
                                    + (uint32_t)ks * 32u + boff;
                        ldsm4(r0, r1, r2, r3, bd);
#pragma unroll
                        for (int mi = 0; mi < 2; ++mi) {
                            mma16816(acc[mi][ng * 2],     a[mi], r0, r1);
                            mma16816(acc[mi][ng * 2 + 1], a[mi], r2, r3);
                        }
                    }
                }
            }
        }

        // prefetch next step's B(0) -> buf0 (buf0 free; overlaps epilogue)
        if (step + 1 < STEPSn) ISSUE_B(0, 0);

        // ---- epilogue: h2, g2, v/div partials (single pass) ----
        {
            float v0p[4], v1p[4], dvp[4];
#pragma unroll
            for (int i = 0; i < 4; ++i) { v0p[i] = 0.f; v1p[i] = 0.f; dvp[i] = 0.f; }
#pragma unroll
            for (int mi = 0; mi < 2; ++mi) {
#pragma unroll
                for (int ni = 0; ni < 4; ++ni) {
                    int j0 = n0w + ni * 8 + tig * 2;
                    float* cA = accA[mi][ni];
                    float* cD = accD[mi][ni];
                    float h00 = ftanh(cA[0] + b2s[j0]);
                    float h01 = ftanh(cA[1] + b2s[j0 + 1]);
                    float h10 = ftanh(cA[2] + b2s[j0]);
                    float h11 = ftanh(cA[3] + b2s[j0 + 1]);
                    v0p[2*mi]   += w30s[j0] * h00 + w30s[j0+1] * h01;
                    v0p[2*mi+1] += w30s[j0] * h10 + w30s[j0+1] * h11;
                    v1p[2*mi]   += w31s[j0] * h00 + w31s[j0+1] * h01;
                    v1p[2*mi+1] += w31s[j0] * h10 + w31s[j0+1] * h11;
                    dvp[2*mi]   += (1.f - h00 * h00) * cD[0] + (1.f - h01 * h01) * cD[1];
                    dvp[2*mi+1] += (1.f - h10 * h10) * cD[2] + (1.f - h11 * h11) * cD[3];
                }
            }
#pragma unroll
            for (int i = 0; i < 4; ++i) {
                v0p[i] += __shfl_xor_sync(0xffffffffu, v0p[i], 1);
                v0p[i] += __shfl_xor_sync(0xffffffffu, v0p[i], 2);
                v1p[i] += __shfl_xor_sync(0xffffffffu, v1p[i], 1);
                v1p[i] += __shfl_xor_sync(0xffffffffu, v1p[i], 2);
                dvp[i] += __shfl_xor_sync(0xffffffffu, dvp[i], 1);
                dvp[i] += __shfl_xor_sync(0xffffffffu, dvp[i], 2);
            }
            if (tig == 0) {
#pragma unroll
                for (int i = 0; i < 4; ++i) {
                    int p = m0w + (i >> 1) * 16 + grp + (i & 1) * 8;
                    part[0 * 512 + warp_n * 64 + p] = v0p[i];
                    part[1 * 512 + warp_n * 64 + p] = v1p[i];
                    part[2 * 512 + warp_n * 64 + p] = dvp[i];
                }
            }
        }
        __syncthreads();

        // ---- state update ----
        if (tid < PPC) {
            float v0 = b30, v1 = b31, dv = 0.f;
#pragma unroll
            for (int wn = 0; wn < 8; ++wn) {
                v0 += part[0 * 512 + wn * 64 + tid];
                v1 += part[1 * 512 + wn * 64 + tid];
                dv += part[2 * 512 + wn * 64 + tid];
            }
            sf[(SM_X0 >> 2) + tid] += v0 * scale * dt;
            sf[(SM_X1 >> 2) + tid] += v1 * scale * dt;
            sf[(SM_SS >> 2) + tid] += dv * scale * dt;
        }
        __syncthreads();
    }

    if (tid < PPC) {
        int gp = gp0 + tid;
        out[gp * 2 + 0] = sf[(SM_X0 >> 2) + tid];
        out[gp * 2 + 1] = sf[(SM_X1 >> 2) + tid];
        if (out_size >= NPTS * PDn + NPTS)
            out[NPTS * PDn + gp] = sf[(SM_SS >> 2) + tid];
    }
#undef ISSUE_B
}

// ---------------------------------------------------------------------------
// kernel_launch
// Inputs (metadata order): x, z, W1, b1, W2, b2, W3, b3, out_scale
// ---------------------------------------------------------------------------
extern "C" void kernel_launch(void* const* d_in, const int* in_sizes, int n_in,
                              void* d_out, int out_size) {
    const float* x   = (const float*)d_in[0];
    const float* z   = (const float*)d_in[1];
    const float* W1  = (const float*)d_in[2];
    const float* b1  = (const float*)d_in[3];
    const float* W2  = (const float*)d_in[4];
    const float* b2  = (const float*)d_in[5];
    const float* W3  = (const float*)d_in[6];
    const float* b3  = (const float*)d_in[7];
    const float* osc = (const float*)d_in[8];
    float* out = (float*)d_out;

    precomp_aux<<<Bn, 256>>>(W1, b1, z);
    precomp_w<<<256, 256>>>(W1, W2, W3);

    cudaFuncSetAttribute(cnf_kernel, cudaFuncAttributeMaxDynamicSharedMemorySize,
                         SM_TOTAL);
    cnf_kernel<<<NCTA, NTHREADS, SM_TOTAL>>>(x, b2, W3, b3, osc, out, out_size);
}

// round 8
// speedup vs baseline: 1.2237x; 1.2237x over previous
#include <cuda_runtime.h>
#include <cuda_fp16.h>
#include <cstdint>

// ---------------------------------------------------------------------------
// Problem constants
// ---------------------------------------------------------------------------
#define Bn     32
#define Nn     2048
#define PDn    2
#define LATn   128
#define Hn     256
#define STEPSn 5
#define DINn   131
#define NPTS   (Bn * Nn)         // 65536
#define PPC    128               // points per CTA (= GEMM M)
#define NCTA   (NPTS / PPC)      // 512
#define KCH    64                // K-chunk
#define NCHUNK (Hn / KCH)        // 4
#define NTHREADS 256
#define NTILES (STEPSn * 2 * NCHUNK)   // 40 B-tiles over the whole kernel

// ---------------------------------------------------------------------------
// Device globals
// ---------------------------------------------------------------------------
// fp16 weights, chunk-major: [matrix(2: W2, M)][chunk(4)][j=256][kk=64]
__device__ __align__(16) __half g_W16[2 * NCHUNK * Hn * KCH];
__device__ __align__(16) float g_base[Bn * Hn];
__device__ __align__(16) float g_c0[Hn], g_c1[Hn], g_ct[Hn], g_csum[Hn];

__device__ __forceinline__ float ftanh(float x) {
    float e = __expf(2.0f * x);
    return 1.0f - __fdividef(2.0f, e + 1.0f);
}
__device__ __forceinline__ uint32_t smem_u32(const void* p) {
    uint32_t a;
    asm("{ .reg .u64 t; cvta.to.shared.u64 t, %1; cvt.u32.u64 %0, t; }"
        : "=r"(a) : "l"(p));
    return a;
}
__device__ __forceinline__ void ldsm4(uint32_t& r0, uint32_t& r1,
                                      uint32_t& r2, uint32_t& r3, uint32_t addr) {
    asm volatile("ldmatrix.sync.aligned.m8n8.x4.shared.b16 {%0,%1,%2,%3}, [%4];"
                 : "=r"(r0), "=r"(r1), "=r"(r2), "=r"(r3) : "r"(addr));
}
__device__ __forceinline__ void mma16816(float* d, const uint32_t* a,
                                         uint32_t b0, uint32_t b1) {
    asm volatile(
        "mma.sync.aligned.m16n8k16.row.col.f32.f16.f16.f32 "
        "{%0,%1,%2,%3},{%4,%5,%6,%7},{%8,%9},{%0,%1,%2,%3};"
        : "+f"(d[0]), "+f"(d[1]), "+f"(d[2]), "+f"(d[3])
        : "r"(a[0]), "r"(a[1]), "r"(a[2]), "r"(a[3]), "r"(b0), "r"(b1));
}
__device__ __forceinline__ void cp16(uint32_t dst, const void* src) {
    asm volatile("cp.async.cg.shared.global [%0], [%1], 16;"
                 :: "r"(dst), "l"(src));
}
#define CP_COMMIT() asm volatile("cp.async.commit_group;" ::: "memory")
#define CP_WAIT0()  asm volatile("cp.async.wait_group 0;" ::: "memory")

// ---------------------------------------------------------------------------
// Precompute 1: per-row W1 decomposition + per-batch base vectors
// ---------------------------------------------------------------------------
__global__ void precomp_aux(const float* __restrict__ W1,
                            const float* __restrict__ b1,
                            const float* __restrict__ z) {
    int k = threadIdx.x;
    int b = blockIdx.x;
    const float* row = W1 + k * DINn;
    float d = b1[k];
    const float* zb = z + b * LATn;
#pragma unroll 16
    for (int l = 0; l < LATn; ++l) d += row[3 + l] * zb[l];
    g_base[b * Hn + k] = d;
    if (b == 0) {
        float s = 0.f;
#pragma unroll 16
        for (int l = 0; l < LATn; ++l) s += row[3 + l];
        g_c0[k] = row[0]; g_c1[k] = row[1]; g_ct[k] = row[2]; g_csum[k] = s;
    }
}

// ---------------------------------------------------------------------------
// Precompute 2: W2 and fused divergence matrix M -> fp16, chunk-major
// ---------------------------------------------------------------------------
__global__ void precomp_w(const float* __restrict__ W1,
                          const float* __restrict__ W2,
                          const float* __restrict__ W3) {
    int j = blockIdx.x;   // 256
    int k = threadIdx.x;  // 256
    float w2 = W2[j * Hn + k];
    float mm = w2 * (W1[k * DINn] * W3[j] + W1[k * DINn + 1] * W3[Hn + j]);
    int chunk = k >> 6, kk = k & 63;
    int idx = chunk * (Hn * KCH) + j * KCH + kk;
    g_W16[idx] = __float2half_rn(w2);
    g_W16[NCHUNK * Hn * KCH + idx] = __float2half_rn(mm);
}

// ---------------------------------------------------------------------------
// SMEM layout (byte offsets) — identical to the 758us kernel plus 2nd B buffer
// ---------------------------------------------------------------------------
#define SM_C0    0
#define SM_C1    1024
#define SM_CT    2048
#define SM_CS    3072
#define SM_BASE  4096
#define SM_B2    5120
#define SM_W30   6144
#define SM_W31   7168
#define SM_X0    8192
#define SM_X1    8704
#define SM_SS    9216
#define SM_PART  9728          // [3][4][128] f32 = 6144
#define SM_AHI   16384         // 128 x 72 halfs = 18432
#define SM_ALO   34816         // 18432
#define SM_B     53248         // 2 bufs x (256 x 72 halfs = 36864) = 73728
#define SM_G2    126976        // 128 x 264 halfs = 67584
#define SM_TOTAL 194560

#define BBUF_SZ  36864

// ---------------------------------------------------------------------------
// Main fused CNF kernel (mma.sync, fp16 hi/lo split A-side, single-term div,
// cp.async double-buffered B stream)
// ---------------------------------------------------------------------------
__global__ void __launch_bounds__(NTHREADS, 1)
cnf_kernel(const float* __restrict__ x,
           const float* __restrict__ b2,
           const float* __restrict__ W3,
           const float* __restrict__ b3,
           const float* __restrict__ osc,
           float* __restrict__ out,
           int out_size) {
    extern __shared__ char smem[];
    float* sf = reinterpret_cast<float*>(smem);
    const uint32_t sb = smem_u32(smem);

    const int tid  = threadIdx.x;
    const int wid  = tid >> 5;
    const int lane = tid & 31;
    const int gp0  = blockIdx.x * PPC;
    const int bidx = gp0 >> 11;

    // load constants into smem
    sf[(SM_C0 >> 2) + tid]   = g_c0[tid];
    sf[(SM_C1 >> 2) + tid]   = g_c1[tid];
    sf[(SM_CT >> 2) + tid]   = g_ct[tid];
    sf[(SM_CS >> 2) + tid]   = g_csum[tid];
    sf[(SM_BASE >> 2) + tid] = g_base[bidx * Hn + tid];
    sf[(SM_B2 >> 2) + tid]   = b2[tid];
    sf[(SM_W30 >> 2) + tid]  = W3[tid];
    sf[(SM_W31 >> 2) + tid]  = W3[Hn + tid];
    if (tid < PPC) {
        int gp = gp0 + tid;
        sf[(SM_X0 >> 2) + tid] = x[gp * 2 + 0];
        sf[(SM_X1 >> 2) + tid] = x[gp * 2 + 1];
        sf[(SM_SS >> 2) + tid] = 0.f;
    }

// issue B-tile q (q in [0,NTILES)) into buffer (q&1) via cp.async
#define ISSUE_B(q) do {                                                    \
        int _q8 = (q) & 7;                                                 \
        int _img = (_q8 >= NCHUNK) ? 1 : 0;                                \
        int _ch  = (q) & 3;                                                \
        const __half* _src = g_W16 + (_img * NCHUNK + _ch) * (Hn * KCH);   \
        uint32_t _dst = sb + SM_B + (uint32_t)((q) & 1) * BBUF_SZ;         \
        _Pragma("unroll")                                                  \
        for (int _i = 0; _i < 8; ++_i) {                                   \
            int _idx = _i * NTHREADS + tid;                                \
            int _j = _idx >> 3, _kb = _idx & 7;                            \
            cp16(_dst + (uint32_t)_j * 144u + (uint32_t)_kb * 16u,         \
                 _src + _idx * 8);                                         \
        }                                                                  \
        CP_COMMIT();                                                       \
    } while (0)

    // prologue: first B tile in flight before anything else
    ISSUE_B(0);
    __syncthreads();

    const float scale = __ldg(osc);
    const float dt  = 1.0f / (float)STEPSn;
    const float b30 = __ldg(b3), b31 = __ldg(b3 + 1);

    // layer-1 mapping
    const int p_mine = tid >> 1;
    const int khalf  = tid & 1;
    // mma warp tiling: 2 (M) x 4 (N), 64x64 warp tiles
    const int warp_m = wid >> 2;
    const int warp_n = wid & 3;
    const int m0w = warp_m * 64;
    const int n0w = warp_n * 64;
    const int grp = lane >> 2, tig = lane & 3;
    const uint32_t aoff = (uint32_t)(lane & 15) * 144u + ((uint32_t)(lane >> 4) << 4);
    const uint32_t boff = ((uint32_t)((lane & 7) + ((lane >> 4) << 3))) * 144u
                        + (((uint32_t)(lane >> 3) & 1u) << 4);

    const float* c0s = sf + (SM_C0 >> 2);
    const float* c1s = sf + (SM_C1 >> 2);
    const float* cts = sf + (SM_CT >> 2);
    const float* css = sf + (SM_CS >> 2);
    const float* bas = sf + (SM_BASE >> 2);
    const float* b2s = sf + (SM_B2 >> 2);
    const float* w30s = sf + (SM_W30 >> 2);
    const float* w31s = sf + (SM_W31 >> 2);
    float* part = sf + (SM_PART >> 2);

#pragma unroll 1
    for (int step = 0; step < STEPSn; ++step) {
        const float tcur = dt * (float)step;
        const float px0 = sf[(SM_X0 >> 2) + p_mine];
        const float px1 = sf[(SM_X1 >> 2) + p_mine];
        const float psv = sf[(SM_SS >> 2) + p_mine];

#pragma unroll 1
        for (int pass = 0; pass < 2; ++pass) {
            float acc[4][8][4];
#pragma unroll
            for (int mi = 0; mi < 4; ++mi)
#pragma unroll
                for (int ni = 0; ni < 8; ++ni)
#pragma unroll
                    for (int q = 0; q < 4; ++q) acc[mi][ni][q] = 0.f;

#pragma unroll 1
            for (int chunk = 0; chunk < NCHUNK; ++chunk) {
                const int q = step * 8 + pass * 4 + chunk;

                // ---- layer-1 activations for this chunk ----
                // pass0: h hi/lo split; pass1: g single fp16 (into AHI)
                {
                    const int kkb = khalf * 32;
#pragma unroll
                    for (int kk2 = 0; kk2 < 32; kk2 += 2) {
                        int kk = kkb + kk2;
                        int k = chunk * KCH + kk;
                        float u0 = bas[k] + tcur * cts[k] + psv * css[k]
                                 + px0 * c0s[k] + px1 * c1s[k];
                        float u1 = bas[k+1] + tcur * cts[k+1] + psv * css[k+1]
                                 + px0 * c0s[k+1] + px1 * c1s[k+1];
                        float h0 = ftanh(u0), h1 = ftanh(u1);
                        uint32_t o = (uint32_t)p_mine * 144u + (uint32_t)kk * 2u;
                        if (pass == 0) {
                            __half H0 = __float2half_rn(h0);
                            __half H1 = __float2half_rn(h1);
                            __half L0 = __float2half_rn(h0 - __half2float(H0));
                            __half L1 = __float2half_rn(h1 - __half2float(H1));
                            *reinterpret_cast<__half2*>(smem + SM_AHI + o) =
                                __halves2half2(H0, H1);
                            *reinterpret_cast<__half2*>(smem + SM_ALO + o) =
                                __halves2half2(L0, L1);
                        } else {
                            float g0 = 1.f - h0 * h0, g1 = 1.f - h1 * h1;
                            *reinterpret_cast<__half2*>(smem + SM_AHI + o) =
                                __floats2half2_rn(g0, g1);
                        }
                    }
                }

                CP_WAIT0();          // B(q) landed
                __syncthreads();     // A stores + B visible to all warps

                // issue B(q+1) early so it hides under MMA(q)
                if (q + 1 < NTILES) ISSUE_B(q + 1);

                // ---- MMA: pass0 = 2 terms (hi,lo); pass1 = 1 term (g) ----
                const uint32_t bb = sb + SM_B + (uint32_t)(q & 1) * BBUF_SZ;
                const int nterms = (pass == 0) ? 2 : 1;
#pragma unroll
                for (int term = 0; term < 2; ++term) {
                    if (term >= nterms) break;
                    const uint32_t ab = sb + (term ? SM_ALO : SM_AHI);
#pragma unroll
                    for (int ks = 0; ks < 4; ++ks) {
                        uint32_t a[4][4];
#pragma unroll
                        for (int mi = 0; mi < 4; ++mi) {
                            uint32_t ad = ab + (uint32_t)(m0w + mi * 16) * 144u
                                        + (uint32_t)ks * 32u + aoff;
                            ldsm4(a[mi][0], a[mi][1], a[mi][2], a[mi][3], ad);
                        }
#pragma unroll
                        for (int ng = 0; ng < 4; ++ng) {
                            uint32_t r0, r1, r2, r3;
                            uint32_t bd = bb + (uint32_t)(n0w + ng * 16) * 144u
                                        + (uint32_t)ks * 32u + boff;
                            ldsm4(r0, r1, r2, r3, bd);
#pragma unroll
                            for (int mi = 0; mi < 4; ++mi) {
                                mma16816(acc[mi][ng * 2],     a[mi], r0, r1);
                                mma16816(acc[mi][ng * 2 + 1], a[mi], r2, r3);
                            }
                        }
                    }
                }
                __syncthreads();     // all warps done before A/B-buffer reuse
            }

            // ---- epilogue ----
            if (pass == 0) {
                float v0p[8], v1p[8];
#pragma unroll
                for (int i = 0; i < 8; ++i) { v0p[i] = 0.f; v1p[i] = 0.f; }
#pragma unroll
                for (int mi = 0; mi < 4; ++mi) {
                    int p0 = m0w + mi * 16 + grp;
#pragma unroll
                    for (int ni = 0; ni < 8; ++ni) {
                        int j0 = n0w + ni * 8 + tig * 2;
                        float* c = acc[mi][ni];
                        float h00 = ftanh(c[0] + b2s[j0]);
                        float h01 = ftanh(c[1] + b2s[j0 + 1]);
                        float h10 = ftanh(c[2] + b2s[j0]);
                        float h11 = ftanh(c[3] + b2s[j0 + 1]);
                        v0p[2*mi]   += w30s[j0] * h00 + w30s[j0+1] * h01;
                        v0p[2*mi+1] += w30s[j0] * h10 + w30s[j0+1] * h11;
                        v1p[2*mi]   += w31s[j0] * h00 + w31s[j0+1] * h01;
                        v1p[2*mi+1] += w31s[j0] * h10 + w31s[j0+1] * h11;
                        uint32_t o0 = (uint32_t)p0 * 528u + (uint32_t)j0 * 2u;
                        *reinterpret_cast<__half2*>(smem + SM_G2 + o0) =
                            __floats2half2_rn(1.f - h00 * h00, 1.f - h01 * h01);
                        *reinterpret_cast<__half2*>(smem + SM_G2 + o0 + 8 * 528u) =
                            __floats2half2_rn(1.f - h10 * h10, 1.f - h11 * h11);
                    }
                }
#pragma unroll
                for (int i = 0; i < 8; ++i) {
                    v0p[i] += __shfl_xor_sync(0xffffffffu, v0p[i], 1);
                    v0p[i] += __shfl_xor_sync(0xffffffffu, v0p[i], 2);
                    v1p[i] += __shfl_xor_sync(0xffffffffu, v1p[i], 1);
                    v1p[i] += __shfl_xor_sync(0xffffffffu, v1p[i], 2);
                }
                if (tig == 0) {
#pragma unroll
                    for (int i = 0; i < 8; ++i) {
                        int p = m0w + (i >> 1) * 16 + grp + (i & 1) * 8;
                        part[0 * 512 + warp_n * 128 + p] = v0p[i];
                        part[1 * 512 + warp_n * 128 + p] = v1p[i];
                    }
                }
            } else {
                float dvp[8];
#pragma unroll
                for (int i = 0; i < 8; ++i) dvp[i] = 0.f;
#pragma unroll
                for (int mi = 0; mi < 4; ++mi) {
                    int p0 = m0w + mi * 16 + grp;
#pragma unroll
                    for (int ni = 0; ni < 8; ++ni) {
                        int j0 = n0w + ni * 8 + tig * 2;
                        float* c = acc[mi][ni];
                        uint32_t o0 = (uint32_t)p0 * 528u + (uint32_t)j0 * 2u;
                        float2 ga = __half22float2(
                            *reinterpret_cast<__half2*>(smem + SM_G2 + o0));
                        float2 gb = __half22float2(
                            *reinterpret_cast<__half2*>(smem + SM_G2 + o0 + 8 * 528u));
                        dvp[2*mi]   += ga.x * c[0] + ga.y * c[1];
                        dvp[2*mi+1] += gb.x * c[2] + gb.y * c[3];
                    }
                }
#pragma unroll
                for (int i = 0; i < 8; ++i) {
                    dvp[i] += __shfl_xor_sync(0xffffffffu, dvp[i], 1);
                    dvp[i] += __shfl_xor_sync(0xffffffffu, dvp[i], 2);
                }
                if (tig == 0) {
#pragma unroll
                    for (int i = 0; i < 8; ++i) {
                        int p = m0w + (i >> 1) * 16 + grp + (i & 1) * 8;
                        part[2 * 512 + warp_n * 128 + p] = dvp[i];
                    }
                }
            }
        }
        __syncthreads();

        // ---- state update ----
        if (tid < PPC) {
            float v0 = b30, v1 = b31, dv = 0.f;
#pragma unroll
            for (int wn = 0; wn < 4; ++wn) {
                v0 += part[0 * 512 + wn * 128 + tid];
                v1 += part[1 * 512 + wn * 128 + tid];
                dv += part[2 * 512 + wn * 128 + tid];
            }
            sf[(SM_X0 >> 2) + tid] += v0 * scale * dt;
            sf[(SM_X1 >> 2) + tid] += v1 * scale * dt;
            sf[(SM_SS >> 2) + tid] += dv * scale * dt;
        }
        __syncthreads();
    }

    if (tid < PPC) {
        int gp = gp0 + tid;
        out[gp * 2 + 0] = sf[(SM_X0 >> 2) + tid];
        out[gp * 2 + 1] = sf[(SM_X1 >> 2) + tid];
        if (out_size >= NPTS * PDn + NPTS)
            out[NPTS * PDn + gp] = sf[(SM_SS >> 2) + tid];
    }
#undef ISSUE_B
}

// ---------------------------------------------------------------------------
// kernel_launch
// Inputs (metadata order): x, z, W1, b1, W2, b2, W3, b3, out_scale
// ---------------------------------------------------------------------------
extern "C" void kernel_launch(void* const* d_in, const int* in_sizes, int n_in,
                              void* d_out, int out_size) {
    const float* x   = (const float*)d_in[0];
    const float* z   = (const float*)d_in[1];
    const float* W1  = (const float*)d_in[2];
    const float* b1  = (const float*)d_in[3];
    const float* W2  = (const float*)d_in[4];
    const float* b2  = (const float*)d_in[5];
    const float* W3  = (const float*)d_in[6];
    const float* b3  = (const float*)d_in[7];
    const float* osc = (const float*)d_in[8];
    float* out = (float*)d_out;

    precomp_aux<<<Bn, 256>>>(W1, b1, z);
    precomp_w<<<256, 256>>>(W1, W2, W3);

    cudaFuncSetAttribute(cnf_kernel, cudaFuncAttributeMaxDynamicSharedMemorySize,
                         SM_TOTAL);
    cnf_kernel<<<NCTA, NTHREADS, SM_TOTAL>>>(x, b2, W3, b3, osc, out, out_size);
}

// round 9
// speedup vs baseline: 1.4736x; 1.2042x over previous
#include <cuda_runtime.h>
#include <cuda_fp16.h>
#include <cstdint>

// ---------------------------------------------------------------------------
// Problem constants
// ---------------------------------------------------------------------------
#define Bn     32
#define Nn     2048
#define PDn    2
#define LATn   128
#define Hn     256
#define STEPSn 5
#define DINn   131
#define NPTS   (Bn * Nn)         // 65536
#define PPC    128               // points per CTA (= GEMM M)
#define NCTA   (NPTS / PPC)      // 512
#define KCH    64                // K-chunk
#define NCHUNK (Hn / KCH)        // 4
#define NTHREADS 256
#define NTILES (STEPSn * 2 * NCHUNK)   // 40 B-tiles over the whole kernel

// ---------------------------------------------------------------------------
// Device globals
// ---------------------------------------------------------------------------
// fp16 weights, chunk-major: [matrix(2: W2, M)][chunk(4)][j=256][kk=64]
__device__ __align__(16) __half g_W16[2 * NCHUNK * Hn * KCH];
__device__ __align__(16) float g_base[Bn * Hn];
__device__ __align__(16) float g_c0[Hn], g_c1[Hn], g_ct[Hn], g_csum[Hn];

__device__ __forceinline__ float ftanh(float x) {
    float e = __expf(2.0f * x);
    return 1.0f - __fdividef(2.0f, e + 1.0f);
}
__device__ __forceinline__ uint32_t smem_u32(const void* p) {
    uint32_t a;
    asm("{ .reg .u64 t; cvta.to.shared.u64 t, %1; cvt.u32.u64 %0, t; }"
        : "=r"(a) : "l"(p));
    return a;
}
__device__ __forceinline__ void ldsm4(uint32_t& r0, uint32_t& r1,
                                      uint32_t& r2, uint32_t& r3, uint32_t addr) {
    asm volatile("ldmatrix.sync.aligned.m8n8.x4.shared.b16 {%0,%1,%2,%3}, [%4];"
                 : "=r"(r0), "=r"(r1), "=r"(r2), "=r"(r3) : "r"(addr));
}
__device__ __forceinline__ void mma16816(float* d, const uint32_t* a,
                                         uint32_t b0, uint32_t b1) {
    asm volatile(
        "mma.sync.aligned.m16n8k16.row.col.f32.f16.f16.f32 "
        "{%0,%1,%2,%3},{%4,%5,%6,%7},{%8,%9},{%0,%1,%2,%3};"
        : "+f"(d[0]), "+f"(d[1]), "+f"(d[2]), "+f"(d[3])
        : "r"(a[0]), "r"(a[1]), "r"(a[2]), "r"(a[3]), "r"(b0), "r"(b1));
}
__device__ __forceinline__ void cp16(uint32_t dst, const void* src) {
    asm volatile("cp.async.cg.shared.global [%0], [%1], 16;"
                 :: "r"(dst), "l"(src));
}
#define CP_COMMIT() asm volatile("cp.async.commit_group;" ::: "memory")
#define CP_WAIT0()  asm volatile("cp.async.wait_group 0;" ::: "memory")

// ---------------------------------------------------------------------------
// Precompute 1: per-row W1 decomposition + per-batch base vectors
// ---------------------------------------------------------------------------
__global__ void precomp_aux(const float* __restrict__ W1,
                            const float* __restrict__ b1,
                            const float* __restrict__ z) {
    int k = threadIdx.x;
    int b = blockIdx.x;
    const float* row = W1 + k * DINn;
    float d = b1[k];
    const float* zb = z + b * LATn;
#pragma unroll 16
    for (int l = 0; l < LATn; ++l) d += row[3 + l] * zb[l];
    g_base[b * Hn + k] = d;
    if (b == 0) {
        float s = 0.f;
#pragma unroll 16
        for (int l = 0; l < LATn; ++l) s += row[3 + l];
        g_c0[k] = row[0]; g_c1[k] = row[1]; g_ct[k] = row[2]; g_csum[k] = s;
    }
}

// ---------------------------------------------------------------------------
// Precompute 2: W2 and fused divergence matrix M -> fp16, chunk-major
// ---------------------------------------------------------------------------
__global__ void precomp_w(const float* __restrict__ W1,
                          const float* __restrict__ W2,
                          const float* __restrict__ W3) {
    int j = blockIdx.x;   // 256
    int k = threadIdx.x;  // 256
    float w2 = W2[j * Hn + k];
    float mm = w2 * (W1[k * DINn] * W3[j] + W1[k * DINn + 1] * W3[Hn + j]);
    int chunk = k >> 6, kk = k & 63;
    int idx = chunk * (Hn * KCH) + j * KCH + kk;
    g_W16[idx] = __float2half_rn(w2);
    g_W16[NCHUNK * Hn * KCH + idx] = __float2half_rn(mm);
}

// ---------------------------------------------------------------------------
// SMEM layout (byte offsets)
// ---------------------------------------------------------------------------
#define SM_C0    0
#define SM_C1    1024
#define SM_CT    2048
#define SM_CS    3072
#define SM_BASE  4096
#define SM_B2    5120
#define SM_W30   6144
#define SM_W31   7168
#define SM_X0    8192
#define SM_X1    8704
#define SM_SS    9216
#define SM_PART  9728          // [3][4][128] f32 = 6144
#define SM_AHI   16384         // 128 x 72 halfs = 18432 (h hi, per-chunk)
#define SM_ALO   34816         // 18432 (h lo, per-chunk)
#define SM_B     53248         // 2 bufs x (256 x 72 halfs = 36864) = 73728
#define SM_AG    126976        // 128 x 264 halfs = 67584 (g1 full-width)
#define SM_TOTAL 194560

#define BBUF_SZ  36864
#define AG_STRIDE 528

// ---------------------------------------------------------------------------
// Main fused CNF kernel: tanh ONCE per step; pass0 = velocity GEMM (2 terms),
// pass1 = divergence GEMM (1 term, reads precomputed full-width g1 tile).
// g2 (layer-2 derivative) carried in registers between the two epilogues.
// ---------------------------------------------------------------------------
__global__ void __launch_bounds__(NTHREADS, 1)
cnf_kernel(const float* __restrict__ x,
           const float* __restrict__ b2,
           const float* __restrict__ W3,
           const float* __restrict__ b3,
           const float* __restrict__ osc,
           float* __restrict__ out,
           int out_size) {
    extern __shared__ char smem[];
    float* sf = reinterpret_cast<float*>(smem);
    const uint32_t sb = smem_u32(smem);

    const int tid  = threadIdx.x;
    const int wid  = tid >> 5;
    const int lane = tid & 31;
    const int gp0  = blockIdx.x * PPC;
    const int bidx = gp0 >> 11;

    // load constants into smem
    sf[(SM_C0 >> 2) + tid]   = g_c0[tid];
    sf[(SM_C1 >> 2) + tid]   = g_c1[tid];
    sf[(SM_CT >> 2) + tid]   = g_ct[tid];
    sf[(SM_CS >> 2) + tid]   = g_csum[tid];
    sf[(SM_BASE >> 2) + tid] = g_base[bidx * Hn + tid];
    sf[(SM_B2 >> 2) + tid]   = b2[tid];
    sf[(SM_W30 >> 2) + tid]  = W3[tid];
    sf[(SM_W31 >> 2) + tid]  = W3[Hn + tid];
    if (tid < PPC) {
        int gp = gp0 + tid;
        sf[(SM_X0 >> 2) + tid] = x[gp * 2 + 0];
        sf[(SM_X1 >> 2) + tid] = x[gp * 2 + 1];
        sf[(SM_SS >> 2) + tid] = 0.f;
    }

// issue B-tile q (q in [0,NTILES)) into buffer (q&1) via cp.async
#define ISSUE_B(q) do {                                                    \
        int _q8 = (q) & 7;                                                 \
        int _img = (_q8 >= NCHUNK) ? 1 : 0;                                \
        int _ch  = (q) & 3;                                                \
        const __half* _src = g_W16 + (_img * NCHUNK + _ch) * (Hn * KCH);   \
        uint32_t _dst = sb + SM_B + (uint32_t)((q) & 1) * BBUF_SZ;         \
        _Pragma("unroll")                                                  \
        for (int _i = 0; _i < 8; ++_i) {                                   \
            int _idx = _i * NTHREADS + tid;                                \
            int _j = _idx >> 3, _kb = _idx & 7;                            \
            cp16(_dst + (uint32_t)_j * 144u + (uint32_t)_kb * 16u,         \
                 _src + _idx * 8);                                         \
        }                                                                  \
        CP_COMMIT();                                                       \
    } while (0)

    // prologue: first B tile in flight before anything else
    ISSUE_B(0);
    __syncthreads();

    const float scale = __ldg(osc);
    const float dt  = 1.0f / (float)STEPSn;
    const float b30 = __ldg(b3), b31 = __ldg(b3 + 1);

    // layer-1 mapping
    const int p_mine = tid >> 1;
    const int khalf  = tid & 1;
    // mma warp tiling: 2 (M) x 4 (N), 64x64 warp tiles
    const int warp_m = wid >> 2;
    const int warp_n = wid & 3;
    const int m0w = warp_m * 64;
    const int n0w = warp_n * 64;
    const int grp = lane >> 2, tig = lane & 3;
    const uint32_t aoff  = (uint32_t)(lane & 15) * 144u + ((uint32_t)(lane >> 4) << 4);
    const uint32_t aoffG = (uint32_t)(lane & 15) * AG_STRIDE + ((uint32_t)(lane >> 4) << 4);
    const uint32_t boff = ((uint32_t)((lane & 7) + ((lane >> 4) << 3))) * 144u
                        + (((uint32_t)(lane >> 3) & 1u) << 4);

    const float* c0s = sf + (SM_C0 >> 2);
    const float* c1s = sf + (SM_C1 >> 2);
    const float* cts = sf + (SM_CT >> 2);
    const float* css = sf + (SM_CS >> 2);
    const float* bas = sf + (SM_BASE >> 2);
    const float* b2s = sf + (SM_B2 >> 2);
    const float* w30s = sf + (SM_W30 >> 2);
    const float* w31s = sf + (SM_W31 >> 2);
    float* part = sf + (SM_PART >> 2);

    uint32_t g2a[4][8], g2b[4][8];   // layer-2 derivative stash (packed half2)

#pragma unroll 1
    for (int step = 0; step < STEPSn; ++step) {
        const float tcur = dt * (float)step;
        const float px0 = sf[(SM_X0 >> 2) + p_mine];
        const float px1 = sf[(SM_X1 >> 2) + p_mine];
        const float psv = sf[(SM_SS >> 2) + p_mine];

        float acc[4][8][4];
#pragma unroll
        for (int mi = 0; mi < 4; ++mi)
#pragma unroll
            for (int ni = 0; ni < 8; ++ni)
#pragma unroll
                for (int q = 0; q < 4; ++q) acc[mi][ni][q] = 0.f;

        // ================= pass 0: velocity GEMM (h1 hi/lo, 2 terms) =======
#pragma unroll 1
        for (int chunk = 0; chunk < NCHUNK; ++chunk) {
            const int q = step * 8 + chunk;

            // ---- layer-1: tanh ONCE; h hi/lo -> chunk tile, g1 -> AG ----
            {
                const int kkb = khalf * 32;
#pragma unroll
                for (int kk2 = 0; kk2 < 32; kk2 += 2) {
                    int kk = kkb + kk2;
                    int k = chunk * KCH + kk;
                    float u0 = bas[k] + tcur * cts[k] + psv * css[k]
                             + px0 * c0s[k] + px1 * c1s[k];
                    float u1 = bas[k+1] + tcur * cts[k+1] + psv * css[k+1]
                             + px0 * c0s[k+1] + px1 * c1s[k+1];
                    float h0 = ftanh(u0), h1 = ftanh(u1);
                    __half H0 = __float2half_rn(h0);
                    __half H1 = __float2half_rn(h1);
                    __half L0 = __float2half_rn(h0 - __half2float(H0));
                    __half L1 = __float2half_rn(h1 - __half2float(H1));
                    uint32_t o = (uint32_t)p_mine * 144u + (uint32_t)kk * 2u;
                    *reinterpret_cast<__half2*>(smem + SM_AHI + o) = __halves2half2(H0, H1);
                    *reinterpret_cast<__half2*>(smem + SM_ALO + o) = __halves2half2(L0, L1);
                    float g0 = 1.f - h0 * h0, g1 = 1.f - h1 * h1;
                    uint32_t og = (uint32_t)p_mine * AG_STRIDE + (uint32_t)k * 2u;
                    *reinterpret_cast<__half2*>(smem + SM_AG + og) =
                        __floats2half2_rn(g0, g1);
                }
            }

            CP_WAIT0();          // B(q) landed
            __syncthreads();     // A stores + B visible to all warps
            ISSUE_B(q + 1);      // hide next B under MMA(q)

            const uint32_t bb = sb + SM_B + (uint32_t)(q & 1) * BBUF_SZ;
#pragma unroll
            for (int term = 0; term < 2; ++term) {
                const uint32_t ab = sb + (term ? SM_ALO : SM_AHI);
#pragma unroll
                for (int ks = 0; ks < 4; ++ks) {
                    uint32_t a[4][4];
#pragma unroll
                    for (int mi = 0; mi < 4; ++mi) {
                        uint32_t ad = ab + (uint32_t)(m0w + mi * 16) * 144u
                                    + (uint32_t)ks * 32u + aoff;
                        ldsm4(a[mi][0], a[mi][1], a[mi][2], a[mi][3], ad);
                    }
#pragma unroll
                    for (int ng = 0; ng < 4; ++ng) {
                        uint32_t r0, r1, r2, r3;
                        uint32_t bd = bb + (uint32_t)(n0w + ng * 16) * 144u
                                    + (uint32_t)ks * 32u + boff;
                        ldsm4(r0, r1, r2, r3, bd);
#pragma unroll
                        for (int mi = 0; mi < 4; ++mi) {
                            mma16816(acc[mi][ng * 2],     a[mi], r0, r1);
                            mma16816(acc[mi][ng * 2 + 1], a[mi], r2, r3);
                        }
                    }
                }
            }
            __syncthreads();     // AHI/ALO rewritten next chunk
        }

        // ---- epilogue 0: h2, v partials; g2 -> registers ----
        {
            float v0p[8], v1p[8];
#pragma unroll
            for (int i = 0; i < 8; ++i) { v0p[i] = 0.f; v1p[i] = 0.f; }
#pragma unroll
            for (int mi = 0; mi < 4; ++mi) {
#pragma unroll
                for (int ni = 0; ni < 8; ++ni) {
                    int j0 = n0w + ni * 8 + tig * 2;
                    float* c = acc[mi][ni];
                    float h00 = ftanh(c[0] + b2s[j0]);
                    float h01 = ftanh(c[1] + b2s[j0 + 1]);
                    float h10 = ftanh(c[2] + b2s[j0]);
                    float h11 = ftanh(c[3] + b2s[j0 + 1]);
                    v0p[2*mi]   += w30s[j0] * h00 + w30s[j0+1] * h01;
                    v0p[2*mi+1] += w30s[j0] * h10 + w30s[j0+1] * h11;
                    v1p[2*mi]   += w31s[j0] * h00 + w31s[j0+1] * h01;
                    v1p[2*mi+1] += w31s[j0] * h10 + w31s[j0+1] * h11;
                    __half2 ga = __floats2half2_rn(1.f - h00 * h00, 1.f - h01 * h01);
                    __half2 gb = __floats2half2_rn(1.f - h10 * h10, 1.f - h11 * h11);
                    g2a[mi][ni] = *reinterpret_cast<uint32_t*>(&ga);
                    g2b[mi][ni] = *reinterpret_cast<uint32_t*>(&gb);
                }
            }
#pragma unroll
            for (int i = 0; i < 8; ++i) {
                v0p[i] += __shfl_xor_sync(0xffffffffu, v0p[i], 1);
                v0p[i] += __shfl_xor_sync(0xffffffffu, v0p[i], 2);
                v1p[i] += __shfl_xor_sync(0xffffffffu, v1p[i], 1);
                v1p[i] += __shfl_xor_sync(0xffffffffu, v1p[i], 2);
            }
            if (tig == 0) {
#pragma unroll
                for (int i = 0; i < 8; ++i) {
                    int p = m0w + (i >> 1) * 16 + grp + (i & 1) * 8;
                    part[0 * 512 + warp_n * 128 + p] = v0p[i];
                    part[1 * 512 + warp_n * 128 + p] = v1p[i];
                }
            }
        }

        // ================= pass 1: divergence GEMM (g1, 1 term) ============
#pragma unroll
        for (int mi = 0; mi < 4; ++mi)
#pragma unroll
            for (int ni = 0; ni < 8; ++ni)
#pragma unroll
                for (int q = 0; q < 4; ++q) acc[mi][ni][q] = 0.f;

#pragma unroll 1
        for (int chunk = 0; chunk < NCHUNK; ++chunk) {
            const int q = step * 8 + 4 + chunk;

            CP_WAIT0();
            __syncthreads();
            if (q + 1 < NTILES) ISSUE_B(q + 1);

            const uint32_t bb = sb + SM_B + (uint32_t)(q & 1) * BBUF_SZ;
            const uint32_t ab = sb + SM_AG + (uint32_t)chunk * 128u;
#pragma unroll
            for (int ks = 0; ks < 4; ++ks) {
                uint32_t a[4][4];
#pragma unroll
                for (int mi = 0; mi < 4; ++mi) {
                    uint32_t ad = ab + (uint32_t)(m0w + mi * 16) * AG_STRIDE
                                + (uint32_t)ks * 32u + aoffG;
                    ldsm4(a[mi][0], a[mi][1], a[mi][2], a[mi][3], ad);
                }
#pragma unroll
                for (int ng = 0; ng < 4; ++ng) {
                    uint32_t r0, r1, r2, r3;
                    uint32_t bd = bb + (uint32_t)(n0w + ng * 16) * 144u
                                + (uint32_t)ks * 32u + boff;
                    ldsm4(r0, r1, r2, r3, bd);
#pragma unroll
                    for (int mi = 0; mi < 4; ++mi) {
                        mma16816(acc[mi][ng * 2],     a[mi], r0, r1);
                        mma16816(acc[mi][ng * 2 + 1], a[mi], r2, r3);
                    }
                }
            }
            // no bottom sync: AG is read-only; B buffers guarded by top sync
        }

        // ---- epilogue 1: dv partials from g2 registers ----
        {
            float dvp[8];
#pragma unroll
            for (int i = 0; i < 8; ++i) dvp[i] = 0.f;
#pragma unroll
            for (int mi = 0; mi < 4; ++mi) {
#pragma unroll
                for (int ni = 0; ni < 8; ++ni) {
                    float* c = acc[mi][ni];
                    float2 ga = __half22float2(
                        *reinterpret_cast<__half2*>(&g2a[mi][ni]));
                    float2 gb = __half22float2(
                        *reinterpret_cast<__half2*>(&g2b[mi][ni]));
                    dvp[2*mi]   += ga.x * c[0] + ga.y * c[1];
                    dvp[2*mi+1] += gb.x * c[2] + gb.y * c[3];
                }
            }
#pragma unroll
            for (int i = 0; i < 8; ++i) {
                dvp[i] += __shfl_xor_sync(0xffffffffu, dvp[i], 1);
                dvp[i] += __shfl_xor_sync(0xffffffffu, dvp[i], 2);
            }
            if (tig == 0) {
#pragma unroll
                for (int i = 0; i < 8; ++i) {
                    int p = m0w + (i >> 1) * 16 + grp + (i & 1) * 8;
                    part[2 * 512 + warp_n * 128 + p] = dvp[i];
                }
            }
        }
        __syncthreads();

        // ---- state update ----
        if (tid < PPC) {
            float v0 = b30, v1 = b31, dv = 0.f;
#pragma unroll
            for (int wn = 0; wn < 4; ++wn) {
                v0 += part[0 * 512 + wn * 128 + tid];
                v1 += part[1 * 512 + wn * 128 + tid];
                dv += part[2 * 512 + wn * 128 + tid];
            }
            sf[(SM_X0 >> 2) + tid] += v0 * scale * dt;
            sf[(SM_X1 >> 2) + tid] += v1 * scale * dt;
            sf[(SM_SS >> 2) + tid] += dv * scale * dt;
        }
        __syncthreads();
    }

    if (tid < PPC) {
        int gp = gp0 + tid;
        out[gp * 2 + 0] = sf[(SM_X0 >> 2) + tid];
        out[gp * 2 + 1] = sf[(SM_X1 >> 2) + tid];
        if (out_size >= NPTS * PDn + NPTS)
            out[NPTS * PDn + gp] = sf[(SM_SS >> 2) + tid];
    }
#undef ISSUE_B
}

// ---------------------------------------------------------------------------
// kernel_launch
// Inputs (metadata order): x, z, W1, b1, W2, b2, W3, b3, out_scale
// ---------------------------------------------------------------------------
extern "C" void kernel_launch(void* const* d_in, const int* in_sizes, int n_in,
                              void* d_out, int out_size) {
    const float* x   = (const float*)d_in[0];
    const float* z   = (const float*)d_in[1];
    const float* W1  = (const float*)d_in[2];
    const float* b1  = (const float*)d_in[3];
    const float* W2  = (const float*)d_in[4];
    const float* b2  = (const float*)d_in[5];
    const float* W3  = (const float*)d_in[6];
    const float* b3  = (const float*)d_in[7];
    const float* osc = (const float*)d_in[8];
    float* out = (float*)d_out;

    precomp_aux<<<Bn, 256>>>(W1, b1, z);
    precomp_w<<<256, 256>>>(W1, W2, W3);

    cudaFuncSetAttribute(cnf_kernel, cudaFuncAttributeMaxDynamicSharedMemorySize,
                         SM_TOTAL);
    cnf_kernel<<<NCTA, NTHREADS, SM_TOTAL>>>(x, b2, W3, b3, osc, out, out_size);
}